// round 3
// baseline (speedup 1.0000x reference)
#include <cuda_runtime.h>
#include <cstdint>

// out[b,a,f] = relu(features[b,a,f] + residuals[0,b,a,f] + residuals[1,b,a,f])
//              if a < n_atoms[b] else 0
// B=256, A=128, F=1024, N_RES=2, fp32.

#define BATCH 256
#define MAX_ATOM 128
#define N_FEAT 1024
#define F4_PER_ROW (N_FEAT / 4)                    // 256
#define TENSOR_F4 (BATCH * MAX_ATOM * F4_PER_ROW)  // 8,388,608 float4 per tensor

__device__ __forceinline__ float4 relu_sum3(float4 f, float4 r0, float4 r1) {
    float4 o;
    o.x = fmaxf(f.x + r0.x + r1.x, 0.f);
    o.y = fmaxf(f.y + r0.y + r1.y, 0.f);
    o.z = fmaxf(f.z + r0.z + r1.z, 0.f);
    o.w = fmaxf(f.w + r0.w + r1.w, 0.f);
    return o;
}

__global__ __launch_bounds__(256, 8)
void dense_block_end_kernel(const float4* __restrict__ feat,
                            const float4* __restrict__ res,   // [2, B, A, F]
                            const int*    __restrict__ ms,    // mol_slice raw (int32 view)
                            float4* __restrict__ out) {
    // Two adjacent rows per block; both rows share the same batch index b.
    const int row0 = blockIdx.x * 2;     // b * MAX_ATOM + a0
    const int b  = row0 >> 7;            // / 128
    const int a0 = row0 & 127;
    const int a1 = a0 + 1;

    // mol_slice layout detection (int32 vs int64 little-endian):
    //  int32 layout: [n0, 1024, n1, 1024, ...]        -> ms[1] == 1024
    //  int64 layout: [n0_lo, 0, 1024_lo, 0, n1_lo,..] -> ms[1] == 0
    const bool is_i32 = (__ldg(&ms[1]) == N_FEAT);
    const int n_atoms = __ldg(&ms[is_i32 ? (2 * b) : (4 * b)]);

    const size_t idx0 = (size_t)row0 * F4_PER_ROW + threadIdx.x;
    const size_t idx1 = idx0 + F4_PER_ROW;
    const float4 zero = make_float4(0.f, 0.f, 0.f, 0.f);

    if (a1 < n_atoms) {
        // Both rows active: 6 independent front-batched LDG.128s.
        const float4 f0  = feat[idx0];
        const float4 f1  = feat[idx1];
        const float4 r00 = res[idx0];
        const float4 r01 = res[idx1];
        const float4 r10 = res[idx0 + (size_t)TENSOR_F4];
        const float4 r11 = res[idx1 + (size_t)TENSOR_F4];
        out[idx0] = relu_sum3(f0, r00, r10);
        out[idx1] = relu_sum3(f1, r01, r11);
    } else if (a0 < n_atoms) {
        // Only row0 active.
        const float4 f0  = feat[idx0];
        const float4 r00 = res[idx0];
        const float4 r10 = res[idx0 + (size_t)TENSOR_F4];
        out[idx0] = relu_sum3(f0, r00, r10);
        out[idx1] = zero;
    } else {
        out[idx0] = zero;
        out[idx1] = zero;
    }
}

extern "C" void kernel_launch(void* const* d_in, const int* in_sizes, int n_in,
                              void* d_out, int out_size) {
    const float4* feat = (const float4*)d_in[0];
    const float4* res  = (const float4*)d_in[1];
    const int*    ms   = (const int*)d_in[2];
    float4* out = (float4*)d_out;

    dim3 grid(BATCH * MAX_ATOM / 2);   // 16384 blocks, two rows per block
    dim3 block(F4_PER_ROW);            // 256 threads
    dense_block_end_kernel<<<grid, block>>>(feat, res, ms, out);
}

// round 8
// speedup vs baseline: 1.0006x; 1.0006x over previous
#include <cuda_runtime.h>
#include <cstdint>

// out[b,a,f] = relu(features[b,a,f] + residuals[0,b,a,f] + residuals[1,b,a,f])
//              if a < n_atoms[b] else 0
// B=256, A=128, F=1024, N_RES=2, fp32.

#define BATCH 256
#define MAX_ATOM 128
#define N_FEAT 1024
#define F4_PER_ROW (N_FEAT / 4)                    // 256
#define TENSOR_F4 (BATCH * MAX_ATOM * F4_PER_ROW)  // 8,388,608 float4 per tensor
#define ROWS_PER_BLOCK 4

__device__ __forceinline__ float4 relu_sum3(float4 f, float4 r0, float4 r1) {
    float4 o;
    o.x = fmaxf(f.x + r0.x + r1.x, 0.f);
    o.y = fmaxf(f.y + r0.y + r1.y, 0.f);
    o.z = fmaxf(f.z + r0.z + r1.z, 0.f);
    o.w = fmaxf(f.w + r0.w + r1.w, 0.f);
    return o;
}

__global__ __launch_bounds__(256, 4)
void dense_block_end_kernel(const float4* __restrict__ feat,
                            const float4* __restrict__ res,   // [2, B, A, F]
                            const int*    __restrict__ ms,    // mol_slice raw (int32 view)
                            float4* __restrict__ out) {
    // Four adjacent rows per block; all share the same batch index b (128 % 4 == 0).
    const int row0 = blockIdx.x * ROWS_PER_BLOCK;   // b * MAX_ATOM + a0
    const int b  = row0 >> 7;                       // / 128
    const int a0 = row0 & 127;

    // mol_slice layout detection (int32 vs int64 little-endian):
    //  int32 layout: [n0, 1024, n1, 1024, ...]        -> ms[1] == 1024
    //  int64 layout: [n0_lo, 0, 1024_lo, 0, n1_lo,..] -> ms[1] == 0
    const bool is_i32 = (__ldg(&ms[1]) == N_FEAT);
    const int n_atoms = __ldg(&ms[is_i32 ? (2 * b) : (4 * b)]);

    const size_t base = (size_t)row0 * F4_PER_ROW + threadIdx.x;
    const float4 zero = make_float4(0.f, 0.f, 0.f, 0.f);

    bool act[ROWS_PER_BLOCK];
    float4 f[ROWS_PER_BLOCK], r0[ROWS_PER_BLOCK], r1[ROWS_PER_BLOCK];

    // Predicated front-batched loads: up to 12 independent LDG.128 in flight.
    #pragma unroll
    for (int i = 0; i < ROWS_PER_BLOCK; i++) {
        act[i] = (a0 + i) < n_atoms;
        const size_t idx = base + (size_t)i * F4_PER_ROW;
        if (act[i]) {
            f[i]  = feat[idx];
            r0[i] = res[idx];
            r1[i] = res[idx + (size_t)TENSOR_F4];
        }
    }

    #pragma unroll
    for (int i = 0; i < ROWS_PER_BLOCK; i++) {
        const size_t idx = base + (size_t)i * F4_PER_ROW;
        out[idx] = act[i] ? relu_sum3(f[i], r0[i], r1[i]) : zero;
    }
}

extern "C" void kernel_launch(void* const* d_in, const int* in_sizes, int n_in,
                              void* d_out, int out_size) {
    const float4* feat = (const float4*)d_in[0];
    const float4* res  = (const float4*)d_in[1];
    const int*    ms   = (const int*)d_in[2];
    float4* out = (float4*)d_out;

    dim3 grid(BATCH * MAX_ATOM / ROWS_PER_BLOCK);  // 8192 blocks
    dim3 block(F4_PER_ROW);                        // 256 threads
    dense_block_end_kernel<<<grid, block>>>(feat, res, ms, out);
}